// round 1
// baseline (speedup 1.0000x reference)
#include <cuda_runtime.h>
#include <cstdint>

// Patcher: x (8,3,1024,1024) fp32, patch=24, stride=16, reflect pad m=4.
// out[((b*64+ph)*64+pw)*1728 + (i*24+j)*3 + c] = xpad[b,c, ph*16+i, pw*16+j]
// where padded coord p maps to source coord q = p-4 with single reflection:
// q<0 -> -q ; q>1023 -> 2046-q.

static constexpr int Bc = 8;
static constexpr int Cc = 3;
static constexpr int Hc = 1024;
static constexpr int Wc = 1024;
static constexpr int Pc = 24;
static constexpr int Sc = 16;
static constexpr int NHc = 64;
static constexpr int NWc = 64;
static constexpr long long TOTAL_ELEMS =
    (long long)Bc * NHc * NWc * Pc * Pc * Cc;  // 56,623,104
static constexpr long long TOTAL_VEC4 = TOTAL_ELEMS / 4;  // 14,155,776

__device__ __forceinline__ int reflect_idx(int q, int last) {
    // single-bounce reflect, pad (=4) << dim
    q = (q < 0) ? -q : q;
    q = (q > last) ? (2 * last - q) : q;
    return q;
}

__global__ void __launch_bounds__(256)
patcher_kernel(const float* __restrict__ x, float* __restrict__ out) {
    long long g = (long long)blockIdx.x * blockDim.x + threadIdx.x;
    if (g >= TOTAL_VEC4) return;

    long long e0 = g * 4;
    // Decompose flat element index e0 -> (b, ph, pw, i, j, c).
    // Group of 4 never crosses a pixel-row (72 = 24*3 divisible by 4),
    // so i, ph, pw, b are constant across the 4 elements; only (j, c) step.
    long long t = e0;
    int c  = (int)(t % Cc);  t /= Cc;
    int j  = (int)(t % Pc);  t /= Pc;
    int i  = (int)(t % Pc);  t /= Pc;
    int pw = (int)(t % NWc); t /= NWc;
    int ph = (int)(t % NHc); t /= NHc;
    int b  = (int)t;

    int y = reflect_idx(ph * Sc + i - 4, Hc - 1);

    const float* xb = x + (long long)b * Cc * Hc * Wc + (long long)y * Wc;
    // channel stride within xb view: Hc*Wc
    const long long CH = (long long)Hc * Wc;

    // j spans at most 2 values across the 4 elements; precompute both x coords
    int x0 = reflect_idx(pw * Sc + j - 4, Wc - 1);
    int x1 = reflect_idx(pw * Sc + j + 1 - 4, Wc - 1);

    float v[4];
    int cc = c;
    int xw = x0;
    bool advanced = false;
    #pragma unroll
    for (int k = 0; k < 4; k++) {
        v[k] = __ldg(xb + (long long)cc * CH + xw);
        cc++;
        if (cc == Cc) { cc = 0; xw = x1; advanced = true; }
    }
    (void)advanced;

    float4 o;
    o.x = v[0]; o.y = v[1]; o.z = v[2]; o.w = v[3];
    reinterpret_cast<float4*>(out)[g] = o;
}

// Fill any tail elements beyond the patches array (flattened (nH, nW) = (64, 64)).
__global__ void tail_kernel(float* __restrict__ out, int extra) {
    int k = threadIdx.x;
    if (k < extra) out[TOTAL_ELEMS + k] = 64.0f;
}

extern "C" void kernel_launch(void* const* d_in, const int* in_sizes, int n_in,
                              void* d_out, int out_size) {
    const float* x = (const float*)d_in[0];
    float* out = (float*)d_out;

    int threads = 256;
    long long blocks = (TOTAL_VEC4 + threads - 1) / threads;  // 55296
    patcher_kernel<<<(unsigned)blocks, threads>>>(x, out);

    long long extra = (long long)out_size - TOTAL_ELEMS;
    if (extra > 0) {
        int e = (int)(extra > 32 ? 32 : extra);
        tail_kernel<<<1, 32>>>(out, e);
    }
}

// round 2
// speedup vs baseline: 1.0505x; 1.0505x over previous
#include <cuda_runtime.h>
#include <cstdint>

// Patcher: x (8,3,1024,1024) fp32, patch=24, stride=16, reflect pad m=4.
// out[((b*64+ph)*64+pw)*1728 + (i*24+j)*3 + c] = xpad[b,c, ph*16+i, pw*16+j]
// padded coord p -> source q = p-4 with single reflection:
//   q<0 -> -q ; q>1023 -> 2046-q.
//
// Thread mapping: one thread = one (b,ph,pw,i,jg) group of 12 output floats
// (4 j-values x 3 channels) = 3x float4 loads (one per channel plane) +
// register transpose + 3x float4 stores. All 32-bit index math.

static constexpr int Cc = 3;
static constexpr int Hc = 1024;
static constexpr int Wc = 1024;
static constexpr unsigned HWc = 1024u * 1024u;
static constexpr long long TOTAL_ELEMS = 56623104LL;   // 8*64*64*576*3
static constexpr unsigned TOTAL_T12 = 4718592u;        // TOTAL_ELEMS / 12
static constexpr unsigned NBLOCKS = TOTAL_T12 / 256u;  // 18432 exact

__device__ __forceinline__ int reflect_idx(int q, int last) {
    q = (q < 0) ? -q : q;
    q = (q > last) ? (2 * last - q) : q;
    return q;
}

__global__ void __launch_bounds__(256)
patcher_kernel(const float* __restrict__ x, float* __restrict__ out,
               unsigned out_size) {
    unsigned g = blockIdx.x * 256u + threadIdx.x;

    // Fused tail: fill any elements past the patches array (flattened (nH,nW)=(64,64)).
    if (g < 32u) {
        unsigned idx = (unsigned)TOTAL_ELEMS + g;
        if (idx < out_size) out[idx] = 64.0f;
    }
    if (g >= TOTAL_T12) return;

    unsigned t = g;
    unsigned jg = t % 6u;  t /= 6u;     // j-group: j0 = 4*jg
    unsigned i  = t % 24u; t /= 24u;    // row within patch
    unsigned pw = t & 63u; t >>= 6;
    unsigned ph = t & 63u; t >>= 6;
    unsigned b  = t;                    // 0..7

    int y = reflect_idx((int)(ph * 16u + i) - 4, Hc - 1);
    const float* row0 = x + (size_t)b * (Cc * HWc) + (size_t)y * Wc;
    const float* row1 = row0 + HWc;
    const float* row2 = row1 + HWc;

    int xbase = (int)(pw * 16u + jg * 4u) - 4;

    float4 A, B, C;  // A = channel0 j0..j3, B = channel1, C = channel2
    if (xbase >= 0 && xbase <= Wc - 4) {
        A = *reinterpret_cast<const float4*>(row0 + xbase);
        B = *reinterpret_cast<const float4*>(row1 + xbase);
        C = *reinterpret_cast<const float4*>(row2 + xbase);
    } else {
        int x0 = reflect_idx(xbase + 0, Wc - 1);
        int x1 = reflect_idx(xbase + 1, Wc - 1);
        int x2 = reflect_idx(xbase + 2, Wc - 1);
        int x3 = reflect_idx(xbase + 3, Wc - 1);
        A.x = row0[x0]; A.y = row0[x1]; A.z = row0[x2]; A.w = row0[x3];
        B.x = row1[x0]; B.y = row1[x1]; B.z = row1[x2]; B.w = row1[x3];
        C.x = row2[x0]; C.y = row2[x1]; C.z = row2[x2]; C.w = row2[x3];
    }

    // Output: patch-major, then (i, j, c) with c fastest.
    unsigned patch = (b << 12) + (ph << 6) + pw;          // b*4096 + ph*64 + pw
    unsigned idx4 = patch * 432u + i * 18u + jg * 3u;     // float4 index

    float4* o4 = reinterpret_cast<float4*>(out);
    float4 o0, o1, o2;
    o0.x = A.x; o0.y = B.x; o0.z = C.x; o0.w = A.y;
    o1.x = B.y; o1.y = C.y; o1.z = A.z; o1.w = B.z;
    o2.x = C.z; o2.y = A.w; o2.z = B.w; o2.w = C.w;
    o4[idx4 + 0] = o0;
    o4[idx4 + 1] = o1;
    o4[idx4 + 2] = o2;
}

extern "C" void kernel_launch(void* const* d_in, const int* in_sizes, int n_in,
                              void* d_out, int out_size) {
    const float* x = (const float*)d_in[0];
    float* out = (float*)d_out;
    patcher_kernel<<<NBLOCKS, 256>>>(x, out, (unsigned)out_size);
}